// round 5
// baseline (speedup 1.0000x reference)
#include <cuda_runtime.h>
#include <cuda_bf16.h>
#include <cstdint>

// Embedding gather: out[b, t, :] = weight[idxes[b, t], :]
// idxes: [8, 2048] int32, weight: [50257, 1024] f32, out: [8,2048,1024] f32
//
// R5: pure bulk-TMA probe. Three LSU-based kernels all plateau at ~18.5us
// kernel / ~49% DRAM. DRAM traffic is ~just the writes (reads are L2-hot
// across graph replays). This version removes the LSU path entirely:
// per CTA, one thread issues 8 cp.async.bulk 4KB row loads (mbarrier
// completion) and 8 cp.async.bulk 4KB row stores (bulk_group). All data
// motion happens in the TMA engines; 56 rows in flight per SM.

#define FEATURES 1024
#define ROW_BYTES (FEATURES * 4)      // 4096
#define ROWS_PER_CTA 8

__global__ __launch_bounds__(32) void embedding_gather_bulk_tma_kernel(
    const int* __restrict__ idxes,
    const float* __restrict__ weight,
    float* __restrict__ out,
    int n_rows)
{
    __shared__ alignas(128) float buf[ROWS_PER_CTA][FEATURES];   // 32 KB
    __shared__ alignas(8) unsigned long long mbar[ROWS_PER_CTA];

    const int base = blockIdx.x * ROWS_PER_CTA;

    if (threadIdx.x == 0) {
        // --- init mbarriers (arrive count 1 each) ---
        uint32_t mbar_addr[ROWS_PER_CTA];
#pragma unroll
        for (int r = 0; r < ROWS_PER_CTA; r++) {
            uint32_t a;
            asm("{ .reg .u64 t; cvta.to.shared.u64 t, %1; cvt.u32.u64 %0, t; }"
                : "=r"(a) : "l"(&mbar[r]));
            mbar_addr[r] = a;
            asm volatile("mbarrier.init.shared.b64 [%0], 1;" :: "r"(a) : "memory");
        }
        // Make mbarrier init visible to the async proxy before TMA use.
        asm volatile("fence.proxy.async.shared::cta;" ::: "memory");

        // --- load indices (vectorized: 2x int4) ---
        int rows_here = n_rows - base;
        if (rows_here > ROWS_PER_CTA) rows_here = ROWS_PER_CTA;

        int idx[ROWS_PER_CTA];
        if (rows_here == ROWS_PER_CTA) {
            int4 i0 = ((const int4*)(idxes + base))[0];
            int4 i1 = ((const int4*)(idxes + base))[1];
            idx[0]=i0.x; idx[1]=i0.y; idx[2]=i0.z; idx[3]=i0.w;
            idx[4]=i1.x; idx[5]=i1.y; idx[6]=i1.z; idx[7]=i1.w;
        } else {
            for (int r = 0; r < rows_here; r++) idx[r] = idxes[base + r];
        }

        // --- issue all bulk G->S row loads (fire-and-forget) ---
#pragma unroll
        for (int r = 0; r < ROWS_PER_CTA; r++) {
            if (r >= rows_here) break;
            asm volatile(
                "mbarrier.arrive.expect_tx.shared.b64 _, [%0], %1;"
                :: "r"(mbar_addr[r]), "r"((uint32_t)ROW_BYTES) : "memory");
            uint32_t sdst;
            asm("{ .reg .u64 t; cvta.to.shared.u64 t, %1; cvt.u32.u64 %0, t; }"
                : "=r"(sdst) : "l"(&buf[r][0]));
            const float* gsrc = weight + (size_t)idx[r] * FEATURES;
            asm volatile(
                "cp.async.bulk.shared::cta.global.mbarrier::complete_tx::bytes "
                "[%0], [%1], %2, [%3];"
                :: "r"(sdst), "l"(gsrc), "r"((uint32_t)ROW_BYTES), "r"(mbar_addr[r])
                : "memory");
        }

        // --- as each load lands, issue its bulk S->G store ---
#pragma unroll
        for (int r = 0; r < ROWS_PER_CTA; r++) {
            if (r >= rows_here) break;
            // wait parity phase 0 on mbar[r]
            {
                uint32_t done;
                asm volatile(
                    "{\n\t"
                    ".reg .pred p;\n\t"
                    "mbarrier.try_wait.parity.shared.b64 p, [%1], 0;\n\t"
                    "selp.b32 %0, 1, 0, p;\n\t"
                    "}"
                    : "=r"(done) : "r"(mbar_addr[r]) : "memory");
                if (!done) {
                    asm volatile(
                        "{\n\t"
                        ".reg .pred P1;\n\t"
                        "WAIT_%=:\n\t"
                        "mbarrier.try_wait.parity.shared.b64 P1, [%0], 0, 0x989680;\n\t"
                        "@P1 bra.uni DONE_%=;\n\t"
                        "bra.uni WAIT_%=;\n\t"
                        "DONE_%=:\n\t"
                        "}"
                        :: "r"(mbar_addr[r]) : "memory");
                }
            }
            uint32_t ssrc;
            asm("{ .reg .u64 t; cvta.to.shared.u64 t, %1; cvt.u32.u64 %0, t; }"
                : "=r"(ssrc) : "l"(&buf[r][0]));
            float* gdst = out + (size_t)(base + r) * FEATURES;
            asm volatile(
                "cp.async.bulk.global.shared::cta.bulk_group [%0], [%1], %2;"
                :: "l"(gdst), "r"(ssrc), "r"((uint32_t)ROW_BYTES) : "memory");
            asm volatile("cp.async.bulk.commit_group;" ::: "memory");
        }

        // smem must stay valid until the TMA store engine has read it.
        asm volatile("cp.async.bulk.wait_group.read 0;" ::: "memory");
    }
    // single warp: lanes reconverge here; no sync needed.
}

extern "C" void kernel_launch(void* const* d_in, const int* in_sizes, int n_in,
                              void* d_out, int out_size)
{
    const int*   idxes  = (const int*)d_in[0];
    const float* weight = (const float*)d_in[1];
    float*       out    = (float*)d_out;

    int n_rows = in_sizes[0];      // 8 * 2048 = 16384
    int n_ctas = (n_rows + ROWS_PER_CTA - 1) / ROWS_PER_CTA;

    embedding_gather_bulk_tma_kernel<<<n_ctas, 32>>>(idxes, weight, out, n_rows);
}

// round 6
// speedup vs baseline: 1.2457x; 1.2457x over previous
#include <cuda_runtime.h>
#include <cuda_bf16.h>
#include <cstdint>

// Embedding gather: out[b, t, :] = weight[idxes[b, t], :]
// idxes: [8, 2048] int32, weight: [50257, 1024] f32, out: [8,2048,1024] f32
//
// R6: streaming stores. Four structurally different kernels (LDG / forced
// LDG batch / cp.async / bulk-TMA) all plateau at 18.5-19us = 128MB through
// the path-independent LTS cap (~6300 B/cyc). The only lever left is byte
// reduction: profiled DRAM (72.8MB) exceeds compulsory writes (64MB) because
// output stores evict the warm weight set from L2. __stcs (evict-first)
// keeps the ~59MB gathered weight rows L2-resident across graph replays,
// eliminating the residual DRAM read traffic.

#define FEATURES 1024
#define VEC4_PER_ROW (FEATURES / 4)   // 256
#define ROWS_PER_CTA 8

__global__ __launch_bounds__(256) void embedding_gather_stcs_kernel(
    const int* __restrict__ idxes,
    const float4* __restrict__ weight,
    float4* __restrict__ out,
    int n_rows)
{
    const int t = threadIdx.x;                     // 0..255 = column slot
    const int base = blockIdx.x * ROWS_PER_CTA;

    if (base + ROWS_PER_CTA <= n_rows) {
        int idx[ROWS_PER_CTA];
#pragma unroll
        for (int r = 0; r < ROWS_PER_CTA; r++)
            idx[r] = idxes[base + r];              // broadcast loads

        float4 v[ROWS_PER_CTA];
#pragma unroll
        for (int r = 0; r < ROWS_PER_CTA; r++)
            v[r] = __ldg(weight + (size_t)idx[r] * VEC4_PER_ROW + t);

        // Streaming (evict-first) stores: output has zero reuse, keep it
        // out of L2 so the weight working set stays resident.
#pragma unroll
        for (int r = 0; r < ROWS_PER_CTA; r++)
            __stcs(out + (size_t)(base + r) * VEC4_PER_ROW + t, v[r]);
    } else {
        // Tail (unused at 16384 rows; kept for safety).
        for (int r = 0; r < ROWS_PER_CTA; r++) {
            int row = base + r;
            if (row >= n_rows) break;
            int src = idxes[row];
            __stcs(out + (size_t)row * VEC4_PER_ROW + t,
                   __ldg(weight + (size_t)src * VEC4_PER_ROW + t));
        }
    }
}

extern "C" void kernel_launch(void* const* d_in, const int* in_sizes, int n_in,
                              void* d_out, int out_size)
{
    const int*    idxes  = (const int*)d_in[0];
    const float4* weight = (const float4*)d_in[1];
    float4*       out    = (float4*)d_out;

    int n_rows = in_sizes[0];      // 8 * 2048 = 16384
    int n_ctas = (n_rows + ROWS_PER_CTA - 1) / ROWS_PER_CTA;

    embedding_gather_stcs_kernel<<<n_ctas, 256>>>(idxes, weight, out, n_rows);
}